// round 2
// baseline (speedup 1.0000x reference)
#include <cuda_runtime.h>
#include <cuda_bf16.h>
#include <stdint.h>

// Problem constants
#define Bp    4
#define Np    50000
#define Ep    800000
#define FIN   128
#define FOUT  128
#define Mrows (Bp * Np)            // 200000 rows for the GEMM

// ---------------------------------------------------------------------------
// Device-global scratch (no cudaMalloc allowed)
// ---------------------------------------------------------------------------
__device__ float g_h[(size_t)Bp * Np * FOUT];   // 102.4 MB: h = x @ W^T
__device__ int   g_counts[Np + 1];
__device__ int   g_offsets[Np + 1];
__device__ int   g_cursor[Np];
__device__ int   g_col[Ep];
__device__ float g_val[Ep];
__device__ int   g_idx64;                        // 1 if edge indices are int64

// ---------------------------------------------------------------------------
// Detect int32 vs int64 edge indices.
// If int64 (values < 2^31, non-negative), every odd int32 word is 0.
// ---------------------------------------------------------------------------
__global__ void detect_kernel(const int* __restrict__ er) {
    __shared__ int any_nonzero;
    if (threadIdx.x == 0) any_nonzero = 0;
    __syncthreads();
    for (int i = threadIdx.x; i < 2048; i += blockDim.x) {
        if (er[2 * i + 1] != 0) any_nonzero = 1;
    }
    __syncthreads();
    if (threadIdx.x == 0) g_idx64 = any_nonzero ? 0 : 1;
}

// ---------------------------------------------------------------------------
// Zero the row-degree histogram
// ---------------------------------------------------------------------------
__global__ void zero_counts_kernel() {
    int i = blockIdx.x * blockDim.x + threadIdx.x;
    if (i <= Np) g_counts[i] = 0;
}

// ---------------------------------------------------------------------------
// Histogram of edge_row
// ---------------------------------------------------------------------------
__global__ void hist_kernel(const int* __restrict__ er) {
    const int idx64 = g_idx64;
    int e = blockIdx.x * blockDim.x + threadIdx.x;
    if (e >= Ep) return;
    int r = idx64 ? er[2 * e] : er[e];
    atomicAdd(&g_counts[r], 1);
}

// ---------------------------------------------------------------------------
// Single-block exclusive scan over counts -> offsets (and cursor copy).
// shfl warp scan + cross-warp scan; 49 chunks of 1024.
// ---------------------------------------------------------------------------
__global__ void scan_kernel() {
    __shared__ int warpsum[32];
    __shared__ int s_run;
    const int t    = threadIdx.x;
    const int lane = t & 31;
    const int w    = t >> 5;
    if (t == 0) s_run = 0;
    __syncthreads();

    for (int base = 0; base < Np; base += 1024) {
        int i = base + t;
        int v = (i < Np) ? g_counts[i] : 0;

        // inclusive warp scan
        int x = v;
        #pragma unroll
        for (int off = 1; off < 32; off <<= 1) {
            int y = __shfl_up_sync(0xFFFFFFFFu, x, off);
            if (lane >= off) x += y;
        }
        if (lane == 31) warpsum[w] = x;
        __syncthreads();
        if (w == 0) {
            int s = warpsum[lane];
            #pragma unroll
            for (int off = 1; off < 32; off <<= 1) {
                int y = __shfl_up_sync(0xFFFFFFFFu, s, off);
                if (lane >= off) s += y;
            }
            warpsum[lane] = s;   // inclusive across warps
        }
        __syncthreads();

        int incl  = x + (w > 0 ? warpsum[w - 1] : 0);
        int run0  = s_run;
        int excl  = run0 + incl - v;
        if (i < Np) {
            g_offsets[i] = excl;
            g_cursor[i]  = excl;
        }
        int total = warpsum[31];
        __syncthreads();
        if (t == 0) s_run = run0 + total;
        __syncthreads();
    }
    if (t == 0) g_offsets[Np] = s_run;
}

// ---------------------------------------------------------------------------
// Scatter edges into CSR order
// ---------------------------------------------------------------------------
__global__ void scatter_kernel(const int* __restrict__ er,
                               const int* __restrict__ ec,
                               const float* __restrict__ ev) {
    const int idx64 = g_idx64;
    int e = blockIdx.x * blockDim.x + threadIdx.x;
    if (e >= Ep) return;
    int r = idx64 ? er[2 * e] : er[e];
    int c = idx64 ? ec[2 * e] : ec[e];
    int p = atomicAdd(&g_cursor[r], 1);
    g_col[p] = c;
    g_val[p] = ev[e];
}

// ---------------------------------------------------------------------------
// GEMM: h[m][o] = sum_k x[m][k] * W[o][k]     (M=200000, K=128, Nout=128)
// BM=128, BN=128, BK=16, 256 threads, 8x8 microtile. 16 KB smem.
// ---------------------------------------------------------------------------
__global__ __launch_bounds__(256, 2)
void gemm_kernel(const float* __restrict__ A, const float* __restrict__ W,
                 float* __restrict__ C) {
    __shared__ float As[16][128];
    __shared__ float Bs[16][128];

    const int tid = threadIdx.x;
    const int tx  = tid & 15;          // 0..15 -> N
    const int ty  = tid >> 4;          // 0..15 -> M
    const long blockM = (long)blockIdx.x * 128;

    float acc[8][8];
    #pragma unroll
    for (int i = 0; i < 8; i++)
        #pragma unroll
        for (int j = 0; j < 8; j++) acc[i][j] = 0.0f;

    for (int k0 = 0; k0 < 128; k0 += 16) {
        // Load A tile (128 rows x 16 k) as float4, transpose into As[k][m]
        #pragma unroll
        for (int v = 0; v < 2; v++) {
            int id  = tid + v * 256;       // 0..511
            int row = id >> 2;
            int kq  = id & 3;
            long gr = blockM + row;
            float4 t = (gr < Mrows)
                ? __ldg(&((const float4*)A)[gr * 32 + (k0 >> 2) + kq])
                : make_float4(0.f, 0.f, 0.f, 0.f);
            As[kq * 4 + 0][row] = t.x;
            As[kq * 4 + 1][row] = t.y;
            As[kq * 4 + 2][row] = t.z;
            As[kq * 4 + 3][row] = t.w;
        }
        // Load B tile: W[n][k0..k0+15] -> Bs[k][n]
        #pragma unroll
        for (int v = 0; v < 2; v++) {
            int id = tid + v * 256;
            int n  = id >> 2;
            int kq = id & 3;
            float4 t = __ldg(&((const float4*)W)[n * 32 + (k0 >> 2) + kq]);
            Bs[kq * 4 + 0][n] = t.x;
            Bs[kq * 4 + 1][n] = t.y;
            Bs[kq * 4 + 2][n] = t.z;
            Bs[kq * 4 + 3][n] = t.w;
        }
        __syncthreads();

        #pragma unroll
        for (int k = 0; k < 16; k++) {
            float a[8], b[8];
            float4 a0 = *(const float4*)&As[k][ty * 8];
            float4 a1 = *(const float4*)&As[k][ty * 8 + 4];
            float4 b0 = *(const float4*)&Bs[k][tx * 8];
            float4 b1 = *(const float4*)&Bs[k][tx * 8 + 4];
            a[0]=a0.x; a[1]=a0.y; a[2]=a0.z; a[3]=a0.w;
            a[4]=a1.x; a[5]=a1.y; a[6]=a1.z; a[7]=a1.w;
            b[0]=b0.x; b[1]=b0.y; b[2]=b0.z; b[3]=b0.w;
            b[4]=b1.x; b[5]=b1.y; b[6]=b1.z; b[7]=b1.w;
            #pragma unroll
            for (int i = 0; i < 8; i++)
                #pragma unroll
                for (int j = 0; j < 8; j++)
                    acc[i][j] += a[i] * b[j];
        }
        __syncthreads();
    }

    #pragma unroll
    for (int i = 0; i < 8; i++) {
        long gr = blockM + ty * 8 + i;
        if (gr < Mrows) {
            float4* crow = (float4*)(C + gr * 128);
            crow[tx * 2 + 0] = make_float4(acc[i][0], acc[i][1], acc[i][2], acc[i][3]);
            crow[tx * 2 + 1] = make_float4(acc[i][4], acc[i][5], acc[i][6], acc[i][7]);
        }
    }
}

// ---------------------------------------------------------------------------
// SpMM: out[b][r][:] = sum_{e in row r} val[e] * h[b][col[e]][:]
// One warp per (row, batch). Lane handles a float4 (128 = 32 lanes * 4).
// ---------------------------------------------------------------------------
__global__ __launch_bounds__(256)
void spmm_kernel(float* __restrict__ out) {
    const int warp = threadIdx.x >> 5;
    const int lane = threadIdx.x & 31;
    const int r = blockIdx.x * 8 + warp;
    const int b = blockIdx.y;
    if (r >= Np) return;

    const float4* __restrict__ hb =
        (const float4*)(g_h + (size_t)b * Np * FOUT);
    const int* __restrict__ cols = g_col;
    const float* __restrict__ vals = g_val;

    int s = g_offsets[r];
    int e = g_offsets[r + 1];

    float4 acc = make_float4(0.f, 0.f, 0.f, 0.f);
    int i = s;
    // 2-way unrolled gather for MLP
    for (; i + 2 <= e; i += 2) {
        int   c0 = __ldg(&cols[i]);
        int   c1 = __ldg(&cols[i + 1]);
        float v0 = __ldg(&vals[i]);
        float v1 = __ldg(&vals[i + 1]);
        float4 t0 = __ldg(&hb[(size_t)c0 * 32 + lane]);
        float4 t1 = __ldg(&hb[(size_t)c1 * 32 + lane]);
        acc.x += v0 * t0.x + v1 * t1.x;
        acc.y += v0 * t0.y + v1 * t1.y;
        acc.z += v0 * t0.z + v1 * t1.z;
        acc.w += v0 * t0.w + v1 * t1.w;
    }
    if (i < e) {
        int   c0 = __ldg(&cols[i]);
        float v0 = __ldg(&vals[i]);
        float4 t0 = __ldg(&hb[(size_t)c0 * 32 + lane]);
        acc.x += v0 * t0.x;
        acc.y += v0 * t0.y;
        acc.z += v0 * t0.z;
        acc.w += v0 * t0.w;
    }
    float4* orow = (float4*)(out + ((size_t)b * Np + r) * FOUT);
    orow[lane] = acc;
}

// ---------------------------------------------------------------------------
// Launch
// ---------------------------------------------------------------------------
extern "C" void kernel_launch(void* const* d_in, const int* in_sizes, int n_in,
                              void* d_out, int out_size) {
    const float* x  = (const float*)d_in[0];   // [4,50000,128]
    const float* W  = (const float*)d_in[1];   // [128,128]
    const int*   er = (const int*)d_in[2];     // edge_row (int32 or int64)
    const int*   ec = (const int*)d_in[3];     // edge_col
    const float* ev = (const float*)d_in[4];   // edge_vals
    float* out = (float*)d_out;

    float* h;
    cudaGetSymbolAddress((void**)&h, g_h);

    // 1) dense projection h = x @ W^T
    gemm_kernel<<<(Mrows + 127) / 128, 256>>>(x, W, h);

    // 2) CSR build
    detect_kernel<<<1, 256>>>(er);
    zero_counts_kernel<<<(Np + 256) / 256, 256>>>();
    hist_kernel<<<(Ep + 255) / 256, 256>>>(er);
    scan_kernel<<<1, 1024>>>();
    scatter_kernel<<<(Ep + 255) / 256, 256>>>(er, ec, ev);

    // 3) SpMM segment sum
    dim3 g((Np + 7) / 8, Bp);
    spmm_kernel<<<g, 256>>>(out);
}

// round 3
// speedup vs baseline: 1.1583x; 1.1583x over previous
#include <cuda_runtime.h>
#include <cuda_fp16.h>
#include <stdint.h>

// Problem constants
#define Bp    4
#define Np    50000
#define Ep    800000
#define FIN   128
#define FOUT  128
#define Mrows (Bp * Np)            // 200000 rows for the GEMM

// ---------------------------------------------------------------------------
// Device-global scratch (no cudaMalloc allowed)
// ---------------------------------------------------------------------------
__device__ __half g_h16[(size_t)Np * Bp * FOUT];  // 51.2 MB, layout [N][B][F]
__device__ int   g_counts[Np + 1];
__device__ int   g_offsets[Np + 1];
__device__ int   g_cursor[Np];
__device__ int   g_bsum[64];
__device__ int   g_col[Ep];
__device__ float g_val[Ep];
__device__ int   g_idx64;                        // 1 if edge indices are int64

// ---------------------------------------------------------------------------
// Zero histogram + detect int32 vs int64 edge indices (block 0).
// If int64 (values < 2^31, non-negative), every odd int32 word is 0.
// ---------------------------------------------------------------------------
__global__ void zero_detect_kernel(const int* __restrict__ er) {
    int i = blockIdx.x * blockDim.x + threadIdx.x;
    if (i <= Np) g_counts[i] = 0;
    if (blockIdx.x == 0) {
        __shared__ int nz;
        if (threadIdx.x == 0) nz = 0;
        __syncthreads();
        for (int j = threadIdx.x; j < 2048; j += blockDim.x)
            if (er[2 * j + 1] != 0) nz = 1;
        __syncthreads();
        if (threadIdx.x == 0) g_idx64 = nz ? 0 : 1;
    }
}

// ---------------------------------------------------------------------------
// Histogram of edge_row — 4 edges per thread, vectorized loads
// ---------------------------------------------------------------------------
__global__ void hist_kernel(const int* __restrict__ er) {
    const int idx64 = g_idx64;
    int base = (blockIdx.x * blockDim.x + threadIdx.x) * 4;
    if (base >= Ep) return;
    if (idx64) {
        if (base + 4 <= Ep) {
            int4 a = __ldg((const int4*)(er + 2 * base));
            int4 b = __ldg((const int4*)(er + 2 * base + 4));
            atomicAdd(&g_counts[a.x], 1);
            atomicAdd(&g_counts[a.z], 1);
            atomicAdd(&g_counts[b.x], 1);
            atomicAdd(&g_counts[b.z], 1);
        } else {
            for (int j = base; j < Ep; j++) atomicAdd(&g_counts[er[2 * j]], 1);
        }
    } else {
        if (base + 4 <= Ep) {
            int4 a = __ldg((const int4*)(er + base));
            atomicAdd(&g_counts[a.x], 1);
            atomicAdd(&g_counts[a.y], 1);
            atomicAdd(&g_counts[a.z], 1);
            atomicAdd(&g_counts[a.w], 1);
        } else {
            for (int j = base; j < Ep; j++) atomicAdd(&g_counts[er[j]], 1);
        }
    }
}

// ---------------------------------------------------------------------------
// Two-level scan. scan1: per-block inclusive scan of 1024 counts.
// ---------------------------------------------------------------------------
__global__ __launch_bounds__(1024)
void scan1_kernel() {
    __shared__ int warpsum[32];
    const int t    = threadIdx.x;
    const int lane = t & 31;
    const int w    = t >> 5;
    int i = blockIdx.x * 1024 + t;
    int v = (i < Np) ? g_counts[i] : 0;

    int x = v;
    #pragma unroll
    for (int off = 1; off < 32; off <<= 1) {
        int y = __shfl_up_sync(0xFFFFFFFFu, x, off);
        if (lane >= off) x += y;
    }
    if (lane == 31) warpsum[w] = x;
    __syncthreads();
    if (w == 0) {
        int s = warpsum[lane];
        #pragma unroll
        for (int off = 1; off < 32; off <<= 1) {
            int y = __shfl_up_sync(0xFFFFFFFFu, s, off);
            if (lane >= off) s += y;
        }
        warpsum[lane] = s;
    }
    __syncthreads();
    int incl = x + (w > 0 ? warpsum[w - 1] : 0);
    if (i < Np) g_offsets[i] = incl;          // inclusive-within-block, temp
    if (t == 1023) g_bsum[blockIdx.x] = incl; // block total
}

// scan2: exclusive scan of the 49 block sums (one block of 64 threads)
__global__ void scan2_kernel(int nblocks) {
    __shared__ int sh[64];
    const int t    = threadIdx.x;
    const int lane = t & 31;
    const int w    = t >> 5;
    int v = (t < nblocks) ? g_bsum[t] : 0;
    int x = v;
    #pragma unroll
    for (int off = 1; off < 32; off <<= 1) {
        int y = __shfl_up_sync(0xFFFFFFFFu, x, off);
        if (lane >= off) x += y;
    }
    sh[t] = x;
    __syncthreads();
    int incl = x + (w == 1 ? sh[31] : 0);
    g_bsum[t] = incl - v;                     // exclusive
    if (t == nblocks - 1) g_offsets[Np] = incl;  // grand total
}

// scan3: finalize exclusive offsets + cursor
__global__ __launch_bounds__(1024)
void scan3_kernel() {
    int i = blockIdx.x * 1024 + threadIdx.x;
    if (i >= Np) return;
    int excl = g_bsum[blockIdx.x] + g_offsets[i] - g_counts[i];
    g_offsets[i] = excl;
    g_cursor[i]  = excl;
}

// ---------------------------------------------------------------------------
// Scatter edges into CSR order
// ---------------------------------------------------------------------------
__global__ void scatter_kernel(const int* __restrict__ er,
                               const int* __restrict__ ec,
                               const float* __restrict__ ev) {
    const int idx64 = g_idx64;
    int e = blockIdx.x * blockDim.x + threadIdx.x;
    if (e >= Ep) return;
    int r = idx64 ? er[2 * e] : er[e];
    int c = idx64 ? ec[2 * e] : ec[e];
    int p = atomicAdd(&g_cursor[r], 1);
    g_col[p] = c;
    g_val[p] = ev[e];
}

// ---------------------------------------------------------------------------
// GEMM: h[m][o] = sum_k x[m][k] * W[o][k]   (M=200000, K=128, Nout=128)
// BM=128, BN=128, BK=16, 256 threads, 8x8 microtile.
// Output written as fp16 into g_h16 with [N][B][F] layout.
// ---------------------------------------------------------------------------
__global__ __launch_bounds__(256, 2)
void gemm_kernel(const float* __restrict__ A, const float* __restrict__ W) {
    __shared__ float As[16][128];
    __shared__ float Bs[16][128];

    const int tid = threadIdx.x;
    const int tx  = tid & 15;          // 0..15 -> N
    const int ty  = tid >> 4;          // 0..15 -> M
    const long blockM = (long)blockIdx.x * 128;

    float acc[8][8];
    #pragma unroll
    for (int i = 0; i < 8; i++)
        #pragma unroll
        for (int j = 0; j < 8; j++) acc[i][j] = 0.0f;

    for (int k0 = 0; k0 < 128; k0 += 16) {
        #pragma unroll
        for (int v = 0; v < 2; v++) {
            int id  = tid + v * 256;
            int row = id >> 2;
            int kq  = id & 3;
            long gr = blockM + row;
            float4 t = (gr < Mrows)
                ? __ldg(&((const float4*)A)[gr * 32 + (k0 >> 2) + kq])
                : make_float4(0.f, 0.f, 0.f, 0.f);
            As[kq * 4 + 0][row] = t.x;
            As[kq * 4 + 1][row] = t.y;
            As[kq * 4 + 2][row] = t.z;
            As[kq * 4 + 3][row] = t.w;
        }
        #pragma unroll
        for (int v = 0; v < 2; v++) {
            int id = tid + v * 256;
            int n  = id >> 2;
            int kq = id & 3;
            float4 t = __ldg(&((const float4*)W)[n * 32 + (k0 >> 2) + kq]);
            Bs[kq * 4 + 0][n] = t.x;
            Bs[kq * 4 + 1][n] = t.y;
            Bs[kq * 4 + 2][n] = t.z;
            Bs[kq * 4 + 3][n] = t.w;
        }
        __syncthreads();

        #pragma unroll
        for (int k = 0; k < 16; k++) {
            float a[8], b[8];
            float4 a0 = *(const float4*)&As[k][ty * 8];
            float4 a1 = *(const float4*)&As[k][ty * 8 + 4];
            float4 b0 = *(const float4*)&Bs[k][tx * 8];
            float4 b1 = *(const float4*)&Bs[k][tx * 8 + 4];
            a[0]=a0.x; a[1]=a0.y; a[2]=a0.z; a[3]=a0.w;
            a[4]=a1.x; a[5]=a1.y; a[6]=a1.z; a[7]=a1.w;
            b[0]=b0.x; b[1]=b0.y; b[2]=b0.z; b[3]=b0.w;
            b[4]=b1.x; b[5]=b1.y; b[6]=b1.z; b[7]=b1.w;
            #pragma unroll
            for (int i = 0; i < 8; i++)
                #pragma unroll
                for (int j = 0; j < 8; j++)
                    acc[i][j] += a[i] * b[j];
        }
        __syncthreads();
    }

    // Epilogue: convert to fp16, write to g_h16[(n*B + b)*128 + f]
    #pragma unroll
    for (int i = 0; i < 8; i++) {
        long gr = blockM + ty * 8 + i;
        if (gr < Mrows) {
            int b = (int)(gr / Np);
            int n = (int)(gr - (long)b * Np);
            __half* hrow = g_h16 + ((size_t)n * Bp + b) * FOUT;
            __half2 h0 = __floats2half2_rn(acc[i][0], acc[i][1]);
            __half2 h1 = __floats2half2_rn(acc[i][2], acc[i][3]);
            __half2 h2 = __floats2half2_rn(acc[i][4], acc[i][5]);
            __half2 h3 = __floats2half2_rn(acc[i][6], acc[i][7]);
            uint4 pack;
            pack.x = *(unsigned*)&h0;
            pack.y = *(unsigned*)&h1;
            pack.z = *(unsigned*)&h2;
            pack.w = *(unsigned*)&h3;
            ((uint4*)hrow)[tx] = pack;   // 16B store, 16 threads cover 256B row
        }
    }
}

// ---------------------------------------------------------------------------
// SpMM: out[b][r][:] = sum_{e in row r} val[e] * h16[col[e]][b][:]
// Block = 256 threads = 8 warps = 2 rows x 4 batches.
// Lane handles 4 features (one 8B half-vector load per edge).
// ---------------------------------------------------------------------------
__global__ __launch_bounds__(256)
void spmm_kernel(float* __restrict__ out) {
    const int warp = threadIdx.x >> 5;
    const int lane = threadIdx.x & 31;
    const int r = blockIdx.x * 2 + (warp >> 2);
    const int b = warp & 3;
    if (r >= Np) return;

    const int*   __restrict__ cols = g_col;
    const float* __restrict__ vals = g_val;
    const __half* __restrict__ h = g_h16;

    int s = g_offsets[r];
    int e = g_offsets[r + 1];

    float4 acc = make_float4(0.f, 0.f, 0.f, 0.f);
    int i = s;
    for (; i + 2 <= e; i += 2) {
        int   c0 = __ldg(&cols[i]);
        int   c1 = __ldg(&cols[i + 1]);
        float v0 = __ldg(&vals[i]);
        float v1 = __ldg(&vals[i + 1]);
        const uint2* p0 = (const uint2*)(h + (((size_t)c0 * Bp + b) << 7));
        const uint2* p1 = (const uint2*)(h + (((size_t)c1 * Bp + b) << 7));
        uint2 q0 = __ldg(&p0[lane]);
        uint2 q1 = __ldg(&p1[lane]);
        float2 f00 = __half22float2(*(__half2*)&q0.x);
        float2 f01 = __half22float2(*(__half2*)&q0.y);
        float2 f10 = __half22float2(*(__half2*)&q1.x);
        float2 f11 = __half22float2(*(__half2*)&q1.y);
        acc.x += v0 * f00.x + v1 * f10.x;
        acc.y += v0 * f00.y + v1 * f10.y;
        acc.z += v0 * f01.x + v1 * f11.x;
        acc.w += v0 * f01.y + v1 * f11.y;
    }
    if (i < e) {
        int   c0 = __ldg(&cols[i]);
        float v0 = __ldg(&vals[i]);
        const uint2* p0 = (const uint2*)(h + (((size_t)c0 * Bp + b) << 7));
        uint2 q0 = __ldg(&p0[lane]);
        float2 f00 = __half22float2(*(__half2*)&q0.x);
        float2 f01 = __half22float2(*(__half2*)&q0.y);
        acc.x += v0 * f00.x;
        acc.y += v0 * f00.y;
        acc.z += v0 * f01.x;
        acc.w += v0 * f01.y;
    }
    float4* orow = (float4*)(out + ((size_t)b * Np + r) * FOUT);
    orow[lane] = acc;   // lane covers features lane*4 .. lane*4+3
}

// ---------------------------------------------------------------------------
// Launch
// ---------------------------------------------------------------------------
extern "C" void kernel_launch(void* const* d_in, const int* in_sizes, int n_in,
                              void* d_out, int out_size) {
    const float* x  = (const float*)d_in[0];   // [4,50000,128]
    const float* W  = (const float*)d_in[1];   // [128,128]
    const int*   er = (const int*)d_in[2];     // edge_row (int32 or int64)
    const int*   ec = (const int*)d_in[3];     // edge_col
    const float* ev = (const float*)d_in[4];   // edge_vals
    float* out = (float*)d_out;

    // 1) dense projection h = x @ W^T  (fp16 store, [N][B][F] layout)
    gemm_kernel<<<(Mrows + 127) / 128, 256>>>(x, W);

    // 2) CSR build
    zero_detect_kernel<<<(Np + 256) / 256, 256>>>(er);
    hist_kernel<<<(Ep / 4 + 255) / 256, 256>>>(er);
    const int nScanBlocks = (Np + 1023) / 1024;   // 49
    scan1_kernel<<<nScanBlocks, 1024>>>();
    scan2_kernel<<<1, 64>>>(nScanBlocks);
    scan3_kernel<<<nScanBlocks, 1024>>>();
    scatter_kernel<<<(Ep + 255) / 256, 256>>>(er, ec, ev);

    // 3) SpMM segment sum
    spmm_kernel<<<(Np + 1) / 2, 256>>>(out);
}

// round 4
// speedup vs baseline: 1.7255x; 1.4897x over previous
#include <cuda_runtime.h>
#include <cuda_fp16.h>
#include <stdint.h>

// Problem constants
#define Bp    4
#define Np    50000
#define Ep    800000
#define FIN   128
#define FOUT  128
#define Mrows (Bp * Np)

#define SROW  136   // halfs per smem row (128 + 8 pad -> conflict-free ldmatrix)

// ---------------------------------------------------------------------------
// Device-global scratch (no cudaMalloc allowed)
// ---------------------------------------------------------------------------
__device__ __half g_h16[(size_t)Np * Bp * FOUT];  // 51.2 MB, layout [N][B][F]
__device__ int   g_counts[Np + 1];
__device__ int   g_offsets[Np + 1];
__device__ int   g_cursor[Np];
__device__ int   g_bsum[64];
__device__ int2  g_colval[Ep];                    // packed {col, val_bits}
__device__ int   g_idx64;

// ---------------------------------------------------------------------------
// Zero histogram + detect int32 vs int64 edge indices (block 0).
// ---------------------------------------------------------------------------
__global__ void zero_detect_kernel(const int* __restrict__ er) {
    int i = blockIdx.x * blockDim.x + threadIdx.x;
    if (i <= Np) g_counts[i] = 0;
    if (blockIdx.x == 0) {
        __shared__ int nz;
        if (threadIdx.x == 0) nz = 0;
        __syncthreads();
        for (int j = threadIdx.x; j < 2048; j += blockDim.x)
            if (er[2 * j + 1] != 0) nz = 1;
        __syncthreads();
        if (threadIdx.x == 0) g_idx64 = nz ? 0 : 1;
    }
}

// ---------------------------------------------------------------------------
// Histogram of edge_row — 4 edges per thread, vectorized loads
// ---------------------------------------------------------------------------
__global__ void hist_kernel(const int* __restrict__ er) {
    const int idx64 = g_idx64;
    int base = (blockIdx.x * blockDim.x + threadIdx.x) * 4;
    if (base >= Ep) return;
    if (idx64) {
        if (base + 4 <= Ep) {
            int4 a = __ldg((const int4*)(er + 2 * base));
            int4 b = __ldg((const int4*)(er + 2 * base + 4));
            atomicAdd(&g_counts[a.x], 1);
            atomicAdd(&g_counts[a.z], 1);
            atomicAdd(&g_counts[b.x], 1);
            atomicAdd(&g_counts[b.z], 1);
        } else {
            for (int j = base; j < Ep; j++) atomicAdd(&g_counts[er[2 * j]], 1);
        }
    } else {
        if (base + 4 <= Ep) {
            int4 a = __ldg((const int4*)(er + base));
            atomicAdd(&g_counts[a.x], 1);
            atomicAdd(&g_counts[a.y], 1);
            atomicAdd(&g_counts[a.z], 1);
            atomicAdd(&g_counts[a.w], 1);
        } else {
            for (int j = base; j < Ep; j++) atomicAdd(&g_counts[er[j]], 1);
        }
    }
}

// ---------------------------------------------------------------------------
// Two-level scan
// ---------------------------------------------------------------------------
__global__ __launch_bounds__(1024)
void scan1_kernel() {
    __shared__ int warpsum[32];
    const int t    = threadIdx.x;
    const int lane = t & 31;
    const int w    = t >> 5;
    int i = blockIdx.x * 1024 + t;
    int v = (i < Np) ? g_counts[i] : 0;

    int x = v;
    #pragma unroll
    for (int off = 1; off < 32; off <<= 1) {
        int y = __shfl_up_sync(0xFFFFFFFFu, x, off);
        if (lane >= off) x += y;
    }
    if (lane == 31) warpsum[w] = x;
    __syncthreads();
    if (w == 0) {
        int s = warpsum[lane];
        #pragma unroll
        for (int off = 1; off < 32; off <<= 1) {
            int y = __shfl_up_sync(0xFFFFFFFFu, s, off);
            if (lane >= off) s += y;
        }
        warpsum[lane] = s;
    }
    __syncthreads();
    int incl = x + (w > 0 ? warpsum[w - 1] : 0);
    if (i < Np) g_offsets[i] = incl;
    if (t == 1023) g_bsum[blockIdx.x] = incl;
}

__global__ void scan2_kernel(int nblocks) {
    __shared__ int sh[64];
    const int t    = threadIdx.x;
    const int lane = t & 31;
    const int w    = t >> 5;
    int v = (t < nblocks) ? g_bsum[t] : 0;
    int x = v;
    #pragma unroll
    for (int off = 1; off < 32; off <<= 1) {
        int y = __shfl_up_sync(0xFFFFFFFFu, x, off);
        if (lane >= off) x += y;
    }
    sh[t] = x;
    __syncthreads();
    int incl = x + (w == 1 ? sh[31] : 0);
    g_bsum[t] = incl - v;
    if (t == nblocks - 1) g_offsets[Np] = incl;
}

__global__ __launch_bounds__(1024)
void scan3_kernel() {
    int i = blockIdx.x * 1024 + threadIdx.x;
    if (i >= Np) return;
    int excl = g_bsum[blockIdx.x] + g_offsets[i] - g_counts[i];
    g_offsets[i] = excl;
    g_cursor[i]  = excl;
}

// ---------------------------------------------------------------------------
// Scatter edges into CSR order (packed 8B stores)
// ---------------------------------------------------------------------------
__global__ void scatter_kernel(const int* __restrict__ er,
                               const int* __restrict__ ec,
                               const float* __restrict__ ev) {
    const int idx64 = g_idx64;
    int e = blockIdx.x * blockDim.x + threadIdx.x;
    if (e >= Ep) return;
    int r = idx64 ? er[2 * e] : er[e];
    int c = idx64 ? ec[2 * e] : ec[e];
    int p = atomicAdd(&g_cursor[r], 1);
    g_colval[p] = make_int2(c, __float_as_int(ev[e]));
}

// ---------------------------------------------------------------------------
// Tensor-core GEMM: h = x @ W^T, fp16 inputs (converted on load), fp32 acc.
// CTA: 128 M-rows x 128 N x K=128 single pass. 256 threads = 8 warps (4x2).
// Warp tile 32x64 via mma.sync.m16n8k16. Output fp16 [N][B][F] via smem stage.
// ---------------------------------------------------------------------------
__global__ __launch_bounds__(256, 2)
void gemm_mma_kernel(const float* __restrict__ A, const float* __restrict__ W) {
    extern __shared__ __half smem[];
    __half* sA = smem;                  // 128 x SROW
    __half* sB = smem + 128 * SROW;     // 128 x SROW

    const int tid  = threadIdx.x;
    const int lane = tid & 31;
    const int wid  = tid >> 5;
    const long blockM = (long)blockIdx.x * 128;

    // ---- load + convert x tile and W into smem ----
    {
        int row   = tid >> 1;
        int cbase = (tid & 1) * 64;
        long gr = blockM + row;
        bool valid = gr < Mrows;
        const float4* src = (const float4*)(A + gr * 128 + cbase);
        __half* dst = sA + row * SROW + cbase;
        #pragma unroll
        for (int i = 0; i < 16; i++) {
            float4 v = valid ? __ldg(src + i) : make_float4(0.f, 0.f, 0.f, 0.f);
            *(__half2*)(dst + i * 4)     = __floats2half2_rn(v.x, v.y);
            *(__half2*)(dst + i * 4 + 2) = __floats2half2_rn(v.z, v.w);
        }
        const float4* wsrc = (const float4*)(W + row * 128 + cbase);
        __half* wdst = sB + row * SROW + cbase;
        #pragma unroll
        for (int i = 0; i < 16; i++) {
            float4 v = __ldg(wsrc + i);
            *(__half2*)(wdst + i * 4)     = __floats2half2_rn(v.x, v.y);
            *(__half2*)(wdst + i * 4 + 2) = __floats2half2_rn(v.z, v.w);
        }
    }
    __syncthreads();

    // ---- mma main loop ----
    const int wm = wid & 3;        // 0..3 -> 32 M-rows each
    const int wn = wid >> 2;       // 0..1 -> 64 N-cols each
    const int a_row = wm * 32;
    const int b_n   = wn * 64;

    float acc[2][8][4];
    #pragma unroll
    for (int i = 0; i < 2; i++)
        #pragma unroll
        for (int j = 0; j < 8; j++)
            #pragma unroll
            for (int q = 0; q < 4; q++) acc[i][j][q] = 0.f;

    uint32_t sA_base = (uint32_t)__cvta_generic_to_shared(sA);
    uint32_t sB_base = (uint32_t)__cvta_generic_to_shared(sB);

    #pragma unroll
    for (int kk = 0; kk < 8; kk++) {
        uint32_t a[2][4];
        #pragma unroll
        for (int i = 0; i < 2; i++) {
            uint32_t addr = sA_base +
                (((a_row + i * 16 + (lane & 15)) * SROW + kk * 16 + (lane >> 4) * 8) << 1);
            asm volatile(
                "ldmatrix.sync.aligned.m8n8.x4.shared.b16 {%0,%1,%2,%3}, [%4];"
                : "=r"(a[i][0]), "=r"(a[i][1]), "=r"(a[i][2]), "=r"(a[i][3])
                : "r"(addr));
        }
        uint32_t b[8][2];
        #pragma unroll
        for (int j = 0; j < 8; j++) {
            int ln   = lane & 7;
            int koff = (lane & 8) ? 8 : 0;
            uint32_t addr = sB_base +
                (((b_n + j * 8 + ln) * SROW + kk * 16 + koff) << 1);
            asm volatile(
                "ldmatrix.sync.aligned.m8n8.x2.shared.b16 {%0,%1}, [%2];"
                : "=r"(b[j][0]), "=r"(b[j][1]) : "r"(addr));
        }
        #pragma unroll
        for (int i = 0; i < 2; i++)
            #pragma unroll
            for (int j = 0; j < 8; j++)
                asm volatile(
                    "mma.sync.aligned.m16n8k16.row.col.f32.f16.f16.f32 "
                    "{%0,%1,%2,%3}, {%4,%5,%6,%7}, {%8,%9}, {%0,%1,%2,%3};"
                    : "+f"(acc[i][j][0]), "+f"(acc[i][j][1]),
                      "+f"(acc[i][j][2]), "+f"(acc[i][j][3])
                    : "r"(a[i][0]), "r"(a[i][1]), "r"(a[i][2]), "r"(a[i][3]),
                      "r"(b[j][0]), "r"(b[j][1]));
    }

    // ---- epilogue: stage fp16 results in sA, then coalesced global stores ----
    __syncthreads();
    #pragma unroll
    for (int i = 0; i < 2; i++) {
        int row0 = a_row + i * 16 + (lane >> 2);
        #pragma unroll
        for (int j = 0; j < 8; j++) {
            int col = b_n + j * 8 + (lane & 3) * 2;
            *(__half2*)(sA + row0 * SROW + col) =
                __floats2half2_rn(acc[i][j][0], acc[i][j][1]);
            *(__half2*)(sA + (row0 + 8) * SROW + col) =
                __floats2half2_rn(acc[i][j][2], acc[i][j][3]);
        }
    }
    __syncthreads();
    {
        int row   = tid >> 1;
        int cbase = (tid & 1) * 64;
        long gr = blockM + row;
        if (gr < Mrows) {
            int b = (int)(gr / Np);
            int n = (int)(gr - (long)b * Np);
            __half* orow = g_h16 + ((size_t)n * Bp + b) * FOUT + cbase;
            const __half* src = sA + row * SROW + cbase;
            #pragma unroll
            for (int i = 0; i < 8; i++)
                ((uint4*)orow)[i] = *(const uint4*)(src + i * 8);
        }
    }
}

// ---------------------------------------------------------------------------
// SpMM: out[b][r][:] = sum_{e in row r} val[e] * h16[col[e]][b][:]
// Block = 256 threads = 8 warps = 2 rows x 4 batches. 4-edge unroll.
// ---------------------------------------------------------------------------
__global__ __launch_bounds__(256)
void spmm_kernel(float* __restrict__ out) {
    const int warp = threadIdx.x >> 5;
    const int lane = threadIdx.x & 31;
    const int r = blockIdx.x * 2 + (warp >> 2);
    const int b = warp & 3;
    if (r >= Np) return;

    const int2*  __restrict__ cv = g_colval;
    const __half* __restrict__ h = g_h16;

    int s = g_offsets[r];
    int e = g_offsets[r + 1];

    float4 acc = make_float4(0.f, 0.f, 0.f, 0.f);
    int i = s;
    for (; i + 4 <= e; i += 4) {
        int2 e0 = __ldg(&cv[i]);
        int2 e1 = __ldg(&cv[i + 1]);
        int2 e2 = __ldg(&cv[i + 2]);
        int2 e3 = __ldg(&cv[i + 3]);
        uint2 q0 = __ldg((const uint2*)(h + (((size_t)e0.x * Bp + b) << 7)) + lane);
        uint2 q1 = __ldg((const uint2*)(h + (((size_t)e1.x * Bp + b) << 7)) + lane);
        uint2 q2 = __ldg((const uint2*)(h + (((size_t)e2.x * Bp + b) << 7)) + lane);
        uint2 q3 = __ldg((const uint2*)(h + (((size_t)e3.x * Bp + b) << 7)) + lane);
        float v0 = __int_as_float(e0.y), v1 = __int_as_float(e1.y);
        float v2 = __int_as_float(e2.y), v3 = __int_as_float(e3.y);
        float2 f;
        f = __half22float2(*(__half2*)&q0.x); acc.x += v0 * f.x; acc.y += v0 * f.y;
        f = __half22float2(*(__half2*)&q0.y); acc.z += v0 * f.x; acc.w += v0 * f.y;
        f = __half22float2(*(__half2*)&q1.x); acc.x += v1 * f.x; acc.y += v1 * f.y;
        f = __half22float2(*(__half2*)&q1.y); acc.z += v1 * f.x; acc.w += v1 * f.y;
        f = __half22float2(*(__half2*)&q2.x); acc.x += v2 * f.x; acc.y += v2 * f.y;
        f = __half22float2(*(__half2*)&q2.y); acc.z += v2 * f.x; acc.w += v2 * f.y;
        f = __half22float2(*(__half2*)&q3.x); acc.x += v3 * f.x; acc.y += v3 * f.y;
        f = __half22float2(*(__half2*)&q3.y); acc.z += v3 * f.x; acc.w += v3 * f.y;
    }
    for (; i < e; i++) {
        int2 e0 = __ldg(&cv[i]);
        float v0 = __int_as_float(e0.y);
        uint2 q0 = __ldg((const uint2*)(h + (((size_t)e0.x * Bp + b) << 7)) + lane);
        float2 f;
        f = __half22float2(*(__half2*)&q0.x); acc.x += v0 * f.x; acc.y += v0 * f.y;
        f = __half22float2(*(__half2*)&q0.y); acc.z += v0 * f.x; acc.w += v0 * f.y;
    }
    float4* orow = (float4*)(out + ((size_t)b * Np + r) * FOUT);
    orow[lane] = acc;
}

// ---------------------------------------------------------------------------
// Launch
// ---------------------------------------------------------------------------
extern "C" void kernel_launch(void* const* d_in, const int* in_sizes, int n_in,
                              void* d_out, int out_size) {
    const float* x  = (const float*)d_in[0];
    const float* W  = (const float*)d_in[1];
    const int*   er = (const int*)d_in[2];
    const int*   ec = (const int*)d_in[3];
    const float* ev = (const float*)d_in[4];
    float* out = (float*)d_out;

    // 1) dense projection h = x @ W^T (tensor cores, fp16 in/out, fp32 acc)
    const int smem_bytes = 2 * 128 * SROW * sizeof(__half);   // 69632
    cudaFuncSetAttribute(gemm_mma_kernel,
                         cudaFuncAttributeMaxDynamicSharedMemorySize, smem_bytes);
    gemm_mma_kernel<<<(Mrows + 127) / 128, 256, smem_bytes>>>(x, W);

    // 2) CSR build
    zero_detect_kernel<<<(Np + 256) / 256, 256>>>(er);
    hist_kernel<<<(Ep / 4 + 255) / 256, 256>>>(er);
    const int nScanBlocks = (Np + 1023) / 1024;   // 49
    scan1_kernel<<<nScanBlocks, 1024>>>();
    scan2_kernel<<<1, 64>>>(nScanBlocks);
    scan3_kernel<<<nScanBlocks, 1024>>>();
    scatter_kernel<<<(Ep + 255) / 256, 256>>>(er, ec, ev);

    // 3) SpMM segment sum
    spmm_kernel<<<(Np + 1) / 2, 256>>>(out);
}